// round 14
// baseline (speedup 1.0000x reference)
#include <cuda_runtime.h>
#include <cuda_bf16.h>
#include <cstdint>

// ---------------------------------------------------------------------------
// Problem constants
// ---------------------------------------------------------------------------
#define BB   32      // batch
#define TT   448     // time
#define DD   768     // input dim
#define HH   256     // hidden
#define G4   1024    // 4*H
#define NTAGS 2

typedef unsigned long long u64;

// ---------------------------------------------------------------------------
// Scratch (device globals; allocation-free)
// ---------------------------------------------------------------------------
__device__ float g_gx[2u * TT * BB * G4];          // [dir][t][b][4H]  117 MB
__device__ float g_hs[2u * BB * TT * HH];          // [dir][b][t][h]   29 MB
__device__ float g_hbuf[2 * 2 * BB * HH];          // [phase][dir][b][h] fp32
__device__ float g_logits[BB * TT * NTAGS];
__device__ float g_kdpart[2048];
__device__ __align__(128) unsigned g_flag[256];    // 8 groups x 16 flags (128B line each)
__device__ __nv_bfloat16 g_xb[(size_t)BB * TT * DD];      // bf16 x     22 MB
__device__ __nv_bfloat16 g_wb[(size_t)2 * G4 * DD];       // bf16 W_ih   3 MB

// ---------------------------------------------------------------------------
// f32x2 packed helpers (recurrence path)
// ---------------------------------------------------------------------------
__device__ __forceinline__ u64 pack2(float lo, float hi) {
    u64 r; asm("mov.b64 %0, {%1, %2};" : "=l"(r) : "f"(lo), "f"(hi)); return r;
}
__device__ __forceinline__ float2 unpack2(u64 v) {
    float2 f; asm("mov.b64 {%0, %1}, %2;" : "=f"(f.x), "=f"(f.y) : "l"(v)); return f;
}
__device__ __forceinline__ void fma2(u64 &acc, u64 a, u64 b) {
    asm("fma.rn.f32x2 %0, %1, %2, %3;" : "=l"(acc) : "l"(a), "l"(b), "l"(acc));
}
__device__ __forceinline__ u64 ldcg64(const void* p) {
    u64 v;
    asm volatile("ld.global.cg.b64 %0, [%1];" : "=l"(v) : "l"(p));
    return v;
}

// ---------------------------------------------------------------------------
// mma.sync / ldmatrix / cp.async helpers (plain sm_80+ PTX, safe on sm_103)
// ---------------------------------------------------------------------------
__device__ __forceinline__ uint32_t smem_u32(const void* p) {
    uint32_t a;
    asm("{ .reg .u64 t; cvta.to.shared.u64 t, %1; cvt.u32.u64 %0, t; }" : "=r"(a) : "l"(p));
    return a;
}
#define CP_ASYNC16(dst, src) \
    asm volatile("cp.async.cg.shared.global [%0], [%1], 16;" :: "r"(dst), "l"(src))
#define CP_COMMIT() asm volatile("cp.async.commit_group;")
#define CP_WAIT(n)  asm volatile("cp.async.wait_group %0;" :: "n"(n))

__device__ __forceinline__ void ldsm_x4(uint32_t &r0, uint32_t &r1, uint32_t &r2, uint32_t &r3,
                                        uint32_t addr) {
    asm volatile("ldmatrix.sync.aligned.m8n8.x4.shared.b16 {%0,%1,%2,%3}, [%4];"
                 : "=r"(r0), "=r"(r1), "=r"(r2), "=r"(r3) : "r"(addr));
}
__device__ __forceinline__ void mma_16816(float* d, const uint32_t* a, uint32_t b0, uint32_t b1) {
    asm volatile("mma.sync.aligned.m16n8k16.row.col.f32.bf16.bf16.f32 "
                 "{%0,%1,%2,%3}, {%4,%5,%6,%7}, {%8,%9}, {%0,%1,%2,%3};"
                 : "+f"(d[0]), "+f"(d[1]), "+f"(d[2]), "+f"(d[3])
                 : "r"(a[0]), "r"(a[1]), "r"(a[2]), "r"(a[3]), "r"(b0), "r"(b1));
}
__device__ __forceinline__ uint32_t sw128(uint32_t off) {
    return off ^ ((off >> 3) & 0x70u);
}

// ---------------------------------------------------------------------------
// init: reset flags + zero h state (both phases)
// ---------------------------------------------------------------------------
__global__ void init_kernel() {
    const int id = blockIdx.x * 256 + threadIdx.x;
    if (blockIdx.x == 0 && threadIdx.x < 256) g_flag[threadIdx.x] = 0u;
    // g_hbuf: 2*2*32*256 floats = 131072 B = 8192 uint4
    uint4* p = (uint4*)g_hbuf;
    for (int i = id; i < 8192; i += gridDim.x * 256)
        p[i] = make_uint4(0u, 0u, 0u, 0u);
}

// ---------------------------------------------------------------------------
// fp32 -> bf16 conversion of x and both W_ih matrices
// ---------------------------------------------------------------------------
#define NX4  ((size_t)BB * TT * DD / 4)     // 2,752,512
#define NW4  ((size_t)G4 * DD / 4)          //   196,608
__global__ void __launch_bounds__(256) cvt_kernel(const float* __restrict__ x,
                                                  const float* __restrict__ Wf,
                                                  const float* __restrict__ Wb)
{
    const size_t total = NX4 + 2 * NW4;
    const size_t stride = (size_t)gridDim.x * 256;
    for (size_t i = (size_t)blockIdx.x * 256 + threadIdx.x; i < total; i += stride) {
        const float4* src; uint2* dst; size_t j;
        if (i < NX4)            { src = (const float4*)x;  j = i;             dst = (uint2*)g_xb; }
        else if (i < NX4 + NW4) { src = (const float4*)Wf; j = i - NX4;       dst = (uint2*)g_wb; }
        else                    { src = (const float4*)Wb; j = i - NX4 - NW4; dst = (uint2*)g_wb + NW4; }
        float4 v = __ldg(src + j);
        __nv_bfloat162 p0 = __floats2bfloat162_rn(v.x, v.y);
        __nv_bfloat162 p1 = __floats2bfloat162_rn(v.z, v.w);
        dst[j] = make_uint2(*(uint32_t*)&p0, *(uint32_t*)&p1);
    }
}

// ---------------------------------------------------------------------------
// bf16 HMMA input GEMM: gx[dir][t][b][n] = x[b,t,:] . Wih[dir][n,:] + biases
// Block: 128x128 tile, 8 warps (warp tile 32x64), K in 12 chunks of 64,
// cp.async THREE-stage SW128-swizzled SMEM, ldmatrix fragment loads.
// ---------------------------------------------------------------------------
#define SM_BIAS  0           // 128 floats (512 B)
#define SM_A0    1024
#define SM_B0    (SM_A0 + 16384)
#define SM_A1    (SM_B0 + 16384)
#define SM_B1    (SM_A1 + 16384)
#define SM_A2    (SM_B1 + 16384)
#define SM_B2    (SM_A2 + 16384)
#define SM_END   (SM_B2 + 16384)
#define GEMM_SMEM (SM_END + 1024)

__global__ void __launch_bounds__(256) gemm_tc_kernel(
    const float* __restrict__ bihf, const float* __restrict__ bhhf,
    const float* __restrict__ bihb, const float* __restrict__ bhhb)
{
    extern __shared__ char smem_raw[];
    uint32_t raw = smem_u32(smem_raw);
    uint32_t pad = (1024u - (raw & 1023u)) & 1023u;
    uint32_t sb = raw + pad;
    char* sm = smem_raw + pad;

    const int tid  = threadIdx.x;
    const int wid  = tid >> 5, lane = tid & 31;
    const int wm   = wid & 3;          // 0..3 -> m offset wm*32
    const int wn   = wid >> 2;         // 0..1 -> n offset wn*64
    const int dir  = blockIdx.z;
    const int m0   = blockIdx.x * 128;
    const int n0   = blockIdx.y * 128;

    const __nv_bfloat16* __restrict__ Wsrc = g_wb + (size_t)dir * G4 * DD;
    const float* __restrict__ bi = dir ? bihb : bihf;
    const float* __restrict__ bh = dir ? bhhb : bhhf;
    float* bias_s = (float*)(sm + SM_BIAS);

    if (tid < 128) bias_s[tid] = bi[n0 + tid] + bh[n0 + tid];

    const uint32_t Aoff[3] = { SM_A0, SM_A1, SM_A2 };
    const uint32_t Boff[3] = { SM_B0, SM_B1, SM_B2 };

    auto load_chunk = [&](int c) {
        const int buf = c % 3;
        const int kc  = c * 64;
        uint32_t Ab = sb + Aoff[buf];
        uint32_t Bb = sb + Boff[buf];
#pragma unroll
        for (int it = 0; it < 4; it++) {
            int idx = tid + it * 256;          // 0..1023
            int r  = idx >> 3;                 // row 0..127
            int cg = idx & 7;                  // 16B col group
            uint32_t swo = sw128((uint32_t)(r * 128 + cg * 16));
            const char* srcA = (const char*)g_xb + ((size_t)(m0 + r) * DD + kc + cg * 8) * 2;
            const char* srcB = (const char*)Wsrc + ((size_t)(n0 + r) * DD + kc + cg * 8) * 2;
            CP_ASYNC16(Ab + swo, srcA);
            CP_ASYNC16(Bb + swo, srcB);
        }
        CP_COMMIT();
    };

    float acc[2][8][4];
#pragma unroll
    for (int i = 0; i < 2; i++)
#pragma unroll
        for (int j = 0; j < 8; j++)
#pragma unroll
            for (int q = 0; q < 4; q++) acc[i][j][q] = 0.f;

    const int a_row_base = wm * 32 + (lane & 15);
    const int a_cb       = (lane >> 4) * 16;
    const int b_row_base = wn * 64 + (lane & 7) + ((lane >> 4) << 3);
    const int b_cb       = ((lane >> 3) & 1) * 16;

    load_chunk(0);
    load_chunk(1);
    load_chunk(2);

    for (int c = 0; c < 12; c++) {
        if (c < 10)      { CP_WAIT(2); }
        else if (c == 10){ CP_WAIT(1); }
        else             { CP_WAIT(0); }
        __syncthreads();
        const uint32_t Ab = sb + Aoff[c % 3];
        const uint32_t Bb = sb + Boff[c % 3];
#pragma unroll
        for (int ks = 0; ks < 4; ks++) {
            const int kbyte = ks * 32;
            uint32_t a[2][4];
#pragma unroll
            for (int mf = 0; mf < 2; mf++) {
                uint32_t off = (uint32_t)((a_row_base + mf * 16) * 128 + a_cb + kbyte);
                ldsm_x4(a[mf][0], a[mf][1], a[mf][2], a[mf][3], Ab + sw128(off));
            }
#pragma unroll
            for (int nf2 = 0; nf2 < 4; nf2++) {
                uint32_t b0, b1, b2, b3;
                uint32_t off = (uint32_t)((b_row_base + nf2 * 16) * 128 + b_cb + kbyte);
                ldsm_x4(b0, b1, b2, b3, Bb + sw128(off));
#pragma unroll
                for (int mf = 0; mf < 2; mf++) {
                    mma_16816(acc[mf][nf2 * 2 + 0], a[mf], b0, b1);
                    mma_16816(acc[mf][nf2 * 2 + 1], a[mf], b2, b3);
                }
            }
        }
        __syncthreads();
        if (c + 3 < 12) load_chunk(c + 3);
    }

    const int qq = lane & 3;
#pragma unroll
    for (int mf = 0; mf < 2; mf++) {
        const int rloc0 = wm * 32 + mf * 16 + (lane >> 2);
        const int row0  = m0 + rloc0;
        const int row1  = row0 + 8;
        const int b0i = row0 / TT, t0 = row0 % TT;
        const int b1i = row1 / TT, t1 = row1 % TT;
        float* dst0 = g_gx + (((size_t)dir * TT + t0) * BB + b0i) * G4 + n0;
        float* dst1 = g_gx + (((size_t)dir * TT + t1) * BB + b1i) * G4 + n0;
#pragma unroll
        for (int nf = 0; nf < 8; nf++) {
            const int cl = wn * 64 + nf * 8 + 2 * qq;
            float bx = bias_s[cl], by = bias_s[cl + 1];
            float2 v0 = { acc[mf][nf][0] + bx, acc[mf][nf][1] + by };
            float2 v1 = { acc[mf][nf][2] + bx, acc[mf][nf][3] + by };
            *(float2*)(dst0 + cl) = v0;
            *(float2*)(dst1 + cl) = v1;
        }
    }
}

// ---------------------------------------------------------------------------
// KD loss partials (2048 deterministic block partials)
// ---------------------------------------------------------------------------
__global__ void __launch_bounds__(256) kd_kernel(const float* __restrict__ s,
                                                 const float* __restrict__ t)
{
    __shared__ float red[256];
    const size_t N4 = (size_t)3 * BB * TT * DD / 4;
    const float4* s4 = (const float4*)s;
    const float4* t4 = (const float4*)t;
    float acc = 0.f;
    for (size_t i = (size_t)blockIdx.x * 256 + threadIdx.x; i < N4; i += 524288) {
        float4 a = __ldg(s4 + i);
        float4 b = __ldg(t4 + i);
        float dx = a.x - b.x, dy = a.y - b.y, dz = a.z - b.z, dw = a.w - b.w;
        acc += dx * dx + dy * dy + dz * dz + dw * dw;
    }
    red[threadIdx.x] = acc;
    __syncthreads();
    for (int o = 128; o; o >>= 1) {
        if (threadIdx.x < o) red[threadIdx.x] += red[threadIdx.x + o];
        __syncthreads();
    }
    if (threadIdx.x == 0) g_kdpart[blockIdx.x] = red[0];
}

// ---------------------------------------------------------------------------
// Persistent BiLSTM recurrence (FFMA2 core, latency-trimmed).
// 128 blocks = 2 dir x 16 hid-groups(16 hidden) x 4 b-groups(8 batches).
// Per step (3 syncs):
//   partials: warp w reads its 32-wide k-slice of h DIRECTLY from g_hbuf
//             (u64 broadcast __ldcg, no smem staging), fma2 into part_s
//   fused reduce+cell: tid<128 sums 4 gates x 8 slices, activations, stores h
//   barrier: 16-flag 128B line, st.release.gpu + 16-lane ld.acquire poll
// ---------------------------------------------------------------------------
__device__ __forceinline__ float sigmoid_f(float x) { return 1.f / (1.f + __expf(-x)); }
__device__ __forceinline__ float tanh_f(float x) {
    x = fminf(15.f, fmaxf(-15.f, x));
    float e = __expf(2.f * x);
    return (e - 1.f) / (e + 1.f);
}

#define PB 68   // part_s batch stride (floats): 64 rows + 4 pad (bank shift)

__global__ void __launch_bounds__(256, 1) recur_kernel(
    const float* __restrict__ Whhf, const float* __restrict__ Whhb)
{
    const int tid = threadIdx.x;
    const int w   = tid >> 5;        // 0..7  k-slice (32 k each)
    const int rl  = tid & 31;        // 0..31 local gate-row
    const int lane = rl;
    const int blk = blockIdx.x;
    const int dir = blk >> 6;                  // 0..1
    const int hg  = (blk & 63) >> 2;           // 0..15  (index within barrier group)
    const int bg  = blk & 3;                   // 0..3
    const int hidbase = hg * 16;
    const int bbase   = bg * 8;
    const int gidx    = dir * 4 + bg;          // barrier group (16 blocks)

    // local row r in 0..63: gate = r>>4, hid = hidbase + (r&15)
    const int R0 = ((rl >> 4) << 8) + hidbase + (rl & 15);   // global gate row of rl
    // row rl+32 -> R0 + 512

    const float* __restrict__ Whh = dir ? Whhb : Whhf;

    // Load this thread's 2x32 weights into registers (packed f32x2)
    u64 WregA[16], WregB[16];
    {
        const float4* wpA = (const float4*)(Whh + (size_t)R0 * HH + w * 32);
        const float4* wpB = (const float4*)(Whh + (size_t)(R0 + 512) * HH + w * 32);
#pragma unroll
        for (int i = 0; i < 8; i++) {
            float4 va = wpA[i];
            WregA[2 * i]     = pack2(va.x, va.y);
            WregA[2 * i + 1] = pack2(va.z, va.w);
            float4 vb = wpB[i];
            WregB[2 * i]     = pack2(vb.x, vb.y);
            WregB[2 * i + 1] = pack2(vb.z, vb.w);
        }
    }

    __shared__ float part_s[8 * 8 * PB];               // [w][b][row64 pad PB]

    float c_state = 0.f;
    const int bl = tid >> 4;   // cell mapping (tid<128): batch-local 0..7
    const int jj = tid & 15;   //                          hid-local  0..15
    unsigned* flagp = &g_flag[gidx * 32];

    for (int s = 0; s < TT; s++) {
        const int t = dir ? (TT - 1 - s) : s;

        // ---- gx prefetch for cell threads (hidden under partials) ----
        float gg0 = 0.f, gg1 = 0.f, gg2 = 0.f, gg3 = 0.f;
        if (tid < 128) {
            const float* gxp = g_gx + (((size_t)dir * TT + t) * BB + bbase + bl) * G4
                             + hidbase + jj;
            gg0 = __ldg(gxp);
            gg1 = __ldg(gxp + 256);
            gg2 = __ldg(gxp + 512);
            gg3 = __ldg(gxp + 768);
        }

        // ---- partial dot products; h read directly from L2 (broadcast) ----
        {
            const float* hbase = g_hbuf + ((size_t)((s & 1) * 2 + dir) * BB + bbase) * HH
                               + w * 32;
#pragma unroll 2
            for (int b = 0; b < 8; b++) {
                const u64* h2 = (const u64*)(hbase + b * HH);
                u64 accA = 0ull, accB = 0ull;
#pragma unroll
                for (int i = 0; i < 16; i++) {
                    u64 hv = ldcg64(h2 + i);
                    fma2(accA, WregA[i], hv);
                    fma2(accB, WregB[i], hv);
                }
                float2 fa = unpack2(accA);
                float2 fb = unpack2(accB);
                part_s[w * (8 * PB) + b * PB + rl]      = fa.x + fa.y;
                part_s[w * (8 * PB) + b * PB + 32 + rl] = fb.x + fb.y;
            }
        }
        __syncthreads();

        // ---- fused reduce + cell update (tid < 128 owns (bl, jj)) ----
        if (tid < 128) {
            float gi = gg0, gf = gg1, gc = gg2, go = gg3;
#pragma unroll
            for (int q = 0; q < 8; q++) {
                const float* ps = part_s + q * (8 * PB) + bl * PB + jj;
                gi += ps[0];
                gf += ps[16];
                gc += ps[32];
                go += ps[48];
            }
            float si = sigmoid_f(gi);
            float sf = sigmoid_f(gf);
            float so = sigmoid_f(go);
            c_state = sf * c_state + si * tanh_f(gc);
            float h = so * tanh_f(c_state);
            int bglob = bbase + bl;
            int hglob = hidbase + jj;
            __stcg(g_hbuf + ((size_t)(((s + 1) & 1) * 2 + dir) * BB + bglob) * HH + hglob, h);
            g_hs[(((size_t)dir * BB + bglob) * TT + t) * HH + hglob] = h;
        }
        __syncthreads();

        // ---- group barrier: 16-flag line, release store + coalesced poll ----
        if (w == 0) {
            unsigned tgt = (unsigned)(s + 1);
            if (lane == 0)
                asm volatile("st.release.gpu.global.u32 [%0], %1;"
                             :: "l"(flagp + hg), "r"(tgt) : "memory");
            unsigned v = tgt;
            do {
                if (lane < 16)
                    asm volatile("ld.acquire.gpu.global.u32 %0, [%1];"
                                 : "=r"(v) : "l"(flagp + lane) : "memory");
            } while (__any_sync(0xffffffffu, v < tgt));
        }
        __syncthreads();
    }
}

// ---------------------------------------------------------------------------
// Logits: one warp per (b,t) row
// ---------------------------------------------------------------------------
__global__ void __launch_bounds__(256) logits_kernel(
    const float* __restrict__ Wcls, const float* __restrict__ bcls)
{
    __shared__ __align__(16) float Ws[2 * 512];
    const int tid = threadIdx.x;
    for (int i = tid; i < 1024; i += 256) Ws[i] = Wcls[i];
    __syncthreads();

    const int warp = tid >> 5, lane = tid & 31;
    const int row = blockIdx.x * 8 + warp;
    const int b = row / TT, t = row % TT;

    const float4* hf  = (const float4*)(g_hs + ((size_t)b * TT + t) * HH);
    const float4* hb  = (const float4*)(g_hs + (((size_t)BB + b) * TT + t) * HH);
    const float4* W0  = (const float4*)Ws;
    const float4* W1  = (const float4*)(Ws + 512);

    float a0 = 0.f, a1 = 0.f;
#pragma unroll
    for (int q = 0; q < 2; q++) {
        int u = lane + q * 32;
        float4 v  = hf[u];
        float4 w0 = W0[u];
        float4 w1 = W1[u];
        a0 += v.x * w0.x + v.y * w0.y + v.z * w0.z + v.w * w0.w;
        a1 += v.x * w1.x + v.y * w1.y + v.z * w1.z + v.w * w1.w;
    }
#pragma unroll
    for (int q = 0; q < 2; q++) {
        int u = lane + q * 32;
        float4 v  = hb[u];
        float4 w0 = W0[64 + u];
        float4 w1 = W1[64 + u];
        a0 += v.x * w0.x + v.y * w0.y + v.z * w0.z + v.w * w0.w;
        a1 += v.x * w1.x + v.y * w1.y + v.z * w1.z + v.w * w1.w;
    }
#pragma unroll
    for (int o = 16; o; o >>= 1) {
        a0 += __shfl_down_sync(0xffffffffu, a0, o);
        a1 += __shfl_down_sync(0xffffffffu, a1, o);
    }
    if (lane == 0) {
        g_logits[row * 2]     = a0 + bcls[0];
        g_logits[row * 2 + 1] = a1 + bcls[1];
    }
}

// ---------------------------------------------------------------------------
// CRF forward + numerator + final loss
// ---------------------------------------------------------------------------
__device__ __forceinline__ float lse2(float a, float b) {
    float m = fmaxf(a, b);
    return m + log1pf(__expf(-fabsf(a - b)));
}

__global__ void crf_kernel(const float* __restrict__ cst,
                           const float* __restrict__ cen,
                           const float* __restrict__ ctr,
                           const int* __restrict__ labels,
                           const int* __restrict__ mask,
                           float* __restrict__ out)
{
    const int b = threadIdx.x;
    const float tr00 = ctr[0], tr01 = ctr[1], tr10 = ctr[2], tr11 = ctr[3];
    const float* em = g_logits + (size_t)b * TT * 2;
    const int* lab = labels + (size_t)b * TT;
    const int* msk = mask   + (size_t)b * TT;

    float e0 = em[0], e1 = em[1];
    float a0 = cst[0] + e0, a1 = cst[1] + e1;

    int tag_prev = lab[0]; if (tag_prev == -100) tag_prev = 0;
    float num = cst[tag_prev] + (tag_prev ? e1 : e0);
    int cnt = 1;

    for (int t = 1; t < TT; t++) {
        int mraw = msk[t];
        float mt = (mraw != 0) ? 1.f : 0.f;
        float em0 = em[t * 2], em1 = em[t * 2 + 1];
        int tag = lab[t]; if (tag == -100) tag = 0;

        float trs = tag ? (tag_prev ? tr11 : tr01) : (tag_prev ? tr10 : tr00);
        float ems = tag ? em1 : em0;
        num += mt * (trs + ems);
        tag_prev = tag;
        cnt += (mraw != 0);

        float n0 = em0 + lse2(a0 + tr00, a1 + tr10);
        float n1 = em1 + lse2(a0 + tr01, a1 + tr11);
        if (mraw != 0) { a0 = n0; a1 = n1; }
    }
    int lt = lab[cnt - 1]; if (lt == -100) lt = 0;
    num += cen[lt];

    float logZ = lse2(a0 + cen[0], a1 + cen[1]);
    float v = num - logZ;

    float kdp = 0.f;
#pragma unroll
    for (int i = 0; i < 64; i++) kdp += g_kdpart[b * 64 + i];

#pragma unroll
    for (int o = 16; o; o >>= 1) {
        v   += __shfl_down_sync(0xffffffffu, v, o);
        kdp += __shfl_down_sync(0xffffffffu, kdp, o);
    }
    if (b == 0) {
        float span = -v / (float)BB;
        float kd = kdp / ((float)3 * BB * TT * DD);
        out[0] = 0.5f * span + 0.5f * kd;
    }
}

// ---------------------------------------------------------------------------
// Launch
// ---------------------------------------------------------------------------
extern "C" void kernel_launch(void* const* d_in, const int* in_sizes, int n_in,
                              void* d_out, int out_size)
{
    const float* top  = (const float*)d_in[0];
    const float* sfe  = (const float*)d_in[1];
    const float* tfe  = (const float*)d_in[2];
    const float* Wihf = (const float*)d_in[3];
    const float* Whhf = (const float*)d_in[4];
    const float* bihf = (const float*)d_in[5];
    const float* bhhf = (const float*)d_in[6];
    const float* Wihb = (const float*)d_in[7];
    const float* Whhb = (const float*)d_in[8];
    const float* bihb = (const float*)d_in[9];
    const float* bhhb = (const float*)d_in[10];
    const float* Wcls = (const float*)d_in[11];
    const float* bcls = (const float*)d_in[12];
    const float* cst  = (const float*)d_in[13];
    const float* cen  = (const float*)d_in[14];
    const float* ctr  = (const float*)d_in[15];
    const int*   lab  = (const int*)d_in[16];
    const int*   msk  = (const int*)d_in[17];
    float* out = (float*)d_out;

    cudaFuncSetAttribute(gemm_tc_kernel, cudaFuncAttributeMaxDynamicSharedMemorySize, GEMM_SMEM);

    init_kernel<<<32, 256>>>();

    cvt_kernel<<<2048, 256>>>(top, Wihf, Wihb);

    dim3 gg(14336 / 128, G4 / 128, 2);               // 112 x 8 x 2
    gemm_tc_kernel<<<gg, 256, GEMM_SMEM>>>(bihf, bhhf, bihb, bhhb);

    kd_kernel<<<2048, 256>>>(sfe, tfe);

    recur_kernel<<<128, 256>>>(Whhf, Whhb);

    logits_kernel<<<(BB * TT) / 8, 256>>>(Wcls, bcls);

    crf_kernel<<<1, 32>>>(cst, cen, ctr, lab, msk, out);
}

// round 15
// speedup vs baseline: 1.6337x; 1.6337x over previous
#include <cuda_runtime.h>
#include <cuda_bf16.h>
#include <cstdint>

// ---------------------------------------------------------------------------
// Problem constants
// ---------------------------------------------------------------------------
#define BB   32      // batch
#define TT   448     // time
#define DD   768     // input dim
#define HH   256     // hidden
#define G4   1024    // 4*H
#define NTAGS 2

typedef unsigned long long u64;

// ---------------------------------------------------------------------------
// Scratch (device globals; allocation-free)
// ---------------------------------------------------------------------------
__device__ float g_gx[2u * TT * BB * G4];          // [dir][t][b][4H]  117 MB
__device__ float g_hs[2u * BB * TT * HH];          // [dir][b][t][h]   29 MB
__device__ float g_hbuf[2 * 2 * BB * HH];          // [phase][dir][b][h] fp32
__device__ float g_logits[BB * TT * NTAGS];
__device__ float g_kdpart[2048];
__device__ unsigned int g_barg[256];               // 8 group counters, 128B apart
__device__ __nv_bfloat16 g_xb[(size_t)BB * TT * DD];      // bf16 x     22 MB
__device__ __nv_bfloat16 g_wb[(size_t)2 * G4 * DD];       // bf16 W_ih   3 MB

// ---------------------------------------------------------------------------
// f32x2 packed helpers (recurrence path)
// ---------------------------------------------------------------------------
__device__ __forceinline__ u64 pack2(float lo, float hi) {
    u64 r; asm("mov.b64 %0, {%1, %2};" : "=l"(r) : "f"(lo), "f"(hi)); return r;
}
__device__ __forceinline__ float2 unpack2(u64 v) {
    float2 f; asm("mov.b64 {%0, %1}, %2;" : "=f"(f.x), "=f"(f.y) : "l"(v)); return f;
}
__device__ __forceinline__ void fma2(u64 &acc, u64 a, u64 b) {
    asm("fma.rn.f32x2 %0, %1, %2, %3;" : "=l"(acc) : "l"(a), "l"(b), "l"(acc));
}

// ---------------------------------------------------------------------------
// mma.sync / ldmatrix / cp.async helpers (plain sm_80+ PTX, safe on sm_103)
// ---------------------------------------------------------------------------
__device__ __forceinline__ uint32_t smem_u32(const void* p) {
    uint32_t a;
    asm("{ .reg .u64 t; cvta.to.shared.u64 t, %1; cvt.u32.u64 %0, t; }" : "=r"(a) : "l"(p));
    return a;
}
#define CP_ASYNC16(dst, src) \
    asm volatile("cp.async.cg.shared.global [%0], [%1], 16;" :: "r"(dst), "l"(src))
#define CP_COMMIT() asm volatile("cp.async.commit_group;")
#define CP_WAIT(n)  asm volatile("cp.async.wait_group %0;" :: "n"(n))

__device__ __forceinline__ void ldsm_x4(uint32_t &r0, uint32_t &r1, uint32_t &r2, uint32_t &r3,
                                        uint32_t addr) {
    asm volatile("ldmatrix.sync.aligned.m8n8.x4.shared.b16 {%0,%1,%2,%3}, [%4];"
                 : "=r"(r0), "=r"(r1), "=r"(r2), "=r"(r3) : "r"(addr));
}
__device__ __forceinline__ void mma_16816(float* d, const uint32_t* a, uint32_t b0, uint32_t b1) {
    asm volatile("mma.sync.aligned.m16n8k16.row.col.f32.bf16.bf16.f32 "
                 "{%0,%1,%2,%3}, {%4,%5,%6,%7}, {%8,%9}, {%0,%1,%2,%3};"
                 : "+f"(d[0]), "+f"(d[1]), "+f"(d[2]), "+f"(d[3])
                 : "r"(a[0]), "r"(a[1]), "r"(a[2]), "r"(a[3]), "r"(b0), "r"(b1));
}
__device__ __forceinline__ uint32_t sw128(uint32_t off) {
    return off ^ ((off >> 3) & 0x70u);
}

// ---------------------------------------------------------------------------
// init: reset barriers + zero h state (both phases)
// ---------------------------------------------------------------------------
__global__ void init_kernel() {
    const int id = blockIdx.x * 256 + threadIdx.x;
    if (blockIdx.x == 0 && threadIdx.x < 256) g_barg[threadIdx.x] = 0u;
    // g_hbuf: 2*2*32*256 floats = 131072 B = 8192 uint4
    uint4* p = (uint4*)g_hbuf;
    for (int i = id; i < 8192; i += gridDim.x * 256)
        p[i] = make_uint4(0u, 0u, 0u, 0u);
}

// ---------------------------------------------------------------------------
// fp32 -> bf16 conversion of x and both W_ih matrices
// ---------------------------------------------------------------------------
#define NX4  ((size_t)BB * TT * DD / 4)     // 2,752,512
#define NW4  ((size_t)G4 * DD / 4)          //   196,608
__global__ void __launch_bounds__(256) cvt_kernel(const float* __restrict__ x,
                                                  const float* __restrict__ Wf,
                                                  const float* __restrict__ Wb)
{
    const size_t total = NX4 + 2 * NW4;
    const size_t stride = (size_t)gridDim.x * 256;
    for (size_t i = (size_t)blockIdx.x * 256 + threadIdx.x; i < total; i += stride) {
        const float4* src; uint2* dst; size_t j;
        if (i < NX4)            { src = (const float4*)x;  j = i;             dst = (uint2*)g_xb; }
        else if (i < NX4 + NW4) { src = (const float4*)Wf; j = i - NX4;       dst = (uint2*)g_wb; }
        else                    { src = (const float4*)Wb; j = i - NX4 - NW4; dst = (uint2*)g_wb + NW4; }
        float4 v = __ldg(src + j);
        __nv_bfloat162 p0 = __floats2bfloat162_rn(v.x, v.y);
        __nv_bfloat162 p1 = __floats2bfloat162_rn(v.z, v.w);
        dst[j] = make_uint2(*(uint32_t*)&p0, *(uint32_t*)&p1);
    }
}

// ---------------------------------------------------------------------------
// bf16 HMMA input GEMM: gx[dir][t][b][n] = x[b,t,:] . Wih[dir][n,:] + biases
// Block: 128x128 tile, 8 warps (warp tile 32x64), K in 12 chunks of 64,
// cp.async THREE-stage SW128-swizzled SMEM, ldmatrix fragment loads.
// ---------------------------------------------------------------------------
#define SM_BIAS  0           // 128 floats (512 B)
#define SM_A0    1024
#define SM_B0    (SM_A0 + 16384)
#define SM_A1    (SM_B0 + 16384)
#define SM_B1    (SM_A1 + 16384)
#define SM_A2    (SM_B1 + 16384)
#define SM_B2    (SM_A2 + 16384)
#define SM_END   (SM_B2 + 16384)
#define GEMM_SMEM (SM_END + 1024)

__global__ void __launch_bounds__(256) gemm_tc_kernel(
    const float* __restrict__ bihf, const float* __restrict__ bhhf,
    const float* __restrict__ bihb, const float* __restrict__ bhhb)
{
    extern __shared__ char smem_raw[];
    uint32_t raw = smem_u32(smem_raw);
    uint32_t pad = (1024u - (raw & 1023u)) & 1023u;
    uint32_t sb = raw + pad;
    char* sm = smem_raw + pad;

    const int tid  = threadIdx.x;
    const int wid  = tid >> 5, lane = tid & 31;
    const int wm   = wid & 3;          // 0..3 -> m offset wm*32
    const int wn   = wid >> 2;         // 0..1 -> n offset wn*64
    const int dir  = blockIdx.z;
    const int m0   = blockIdx.x * 128;
    const int n0   = blockIdx.y * 128;

    const __nv_bfloat16* __restrict__ Wsrc = g_wb + (size_t)dir * G4 * DD;
    const float* __restrict__ bi = dir ? bihb : bihf;
    const float* __restrict__ bh = dir ? bhhb : bhhf;
    float* bias_s = (float*)(sm + SM_BIAS);

    if (tid < 128) bias_s[tid] = bi[n0 + tid] + bh[n0 + tid];

    const uint32_t Aoff[3] = { SM_A0, SM_A1, SM_A2 };
    const uint32_t Boff[3] = { SM_B0, SM_B1, SM_B2 };

    auto load_chunk = [&](int c) {
        const int buf = c % 3;
        const int kc  = c * 64;
        uint32_t Ab = sb + Aoff[buf];
        uint32_t Bb = sb + Boff[buf];
#pragma unroll
        for (int it = 0; it < 4; it++) {
            int idx = tid + it * 256;          // 0..1023
            int r  = idx >> 3;                 // row 0..127
            int cg = idx & 7;                  // 16B col group
            uint32_t swo = sw128((uint32_t)(r * 128 + cg * 16));
            const char* srcA = (const char*)g_xb + ((size_t)(m0 + r) * DD + kc + cg * 8) * 2;
            const char* srcB = (const char*)Wsrc + ((size_t)(n0 + r) * DD + kc + cg * 8) * 2;
            CP_ASYNC16(Ab + swo, srcA);
            CP_ASYNC16(Bb + swo, srcB);
        }
        CP_COMMIT();
    };

    float acc[2][8][4];
#pragma unroll
    for (int i = 0; i < 2; i++)
#pragma unroll
        for (int j = 0; j < 8; j++)
#pragma unroll
            for (int q = 0; q < 4; q++) acc[i][j][q] = 0.f;

    const int a_row_base = wm * 32 + (lane & 15);
    const int a_cb       = (lane >> 4) * 16;
    const int b_row_base = wn * 64 + (lane & 7) + ((lane >> 4) << 3);
    const int b_cb       = ((lane >> 3) & 1) * 16;

    load_chunk(0);
    load_chunk(1);
    load_chunk(2);

    for (int c = 0; c < 12; c++) {
        if (c < 10)      { CP_WAIT(2); }
        else if (c == 10){ CP_WAIT(1); }
        else             { CP_WAIT(0); }
        __syncthreads();
        const uint32_t Ab = sb + Aoff[c % 3];
        const uint32_t Bb = sb + Boff[c % 3];
#pragma unroll
        for (int ks = 0; ks < 4; ks++) {
            const int kbyte = ks * 32;
            uint32_t a[2][4];
#pragma unroll
            for (int mf = 0; mf < 2; mf++) {
                uint32_t off = (uint32_t)((a_row_base + mf * 16) * 128 + a_cb + kbyte);
                ldsm_x4(a[mf][0], a[mf][1], a[mf][2], a[mf][3], Ab + sw128(off));
            }
#pragma unroll
            for (int nf2 = 0; nf2 < 4; nf2++) {
                uint32_t b0, b1, b2, b3;
                uint32_t off = (uint32_t)((b_row_base + nf2 * 16) * 128 + b_cb + kbyte);
                ldsm_x4(b0, b1, b2, b3, Bb + sw128(off));
#pragma unroll
                for (int mf = 0; mf < 2; mf++) {
                    mma_16816(acc[mf][nf2 * 2 + 0], a[mf], b0, b1);
                    mma_16816(acc[mf][nf2 * 2 + 1], a[mf], b2, b3);
                }
            }
        }
        __syncthreads();
        if (c + 3 < 12) load_chunk(c + 3);
    }

    const int qq = lane & 3;
#pragma unroll
    for (int mf = 0; mf < 2; mf++) {
        const int rloc0 = wm * 32 + mf * 16 + (lane >> 2);
        const int row0  = m0 + rloc0;
        const int row1  = row0 + 8;
        const int b0i = row0 / TT, t0 = row0 % TT;
        const int b1i = row1 / TT, t1 = row1 % TT;
        float* dst0 = g_gx + (((size_t)dir * TT + t0) * BB + b0i) * G4 + n0;
        float* dst1 = g_gx + (((size_t)dir * TT + t1) * BB + b1i) * G4 + n0;
#pragma unroll
        for (int nf = 0; nf < 8; nf++) {
            const int cl = wn * 64 + nf * 8 + 2 * qq;
            float bx = bias_s[cl], by = bias_s[cl + 1];
            float2 v0 = { acc[mf][nf][0] + bx, acc[mf][nf][1] + by };
            float2 v1 = { acc[mf][nf][2] + bx, acc[mf][nf][3] + by };
            *(float2*)(dst0 + cl) = v0;
            *(float2*)(dst1 + cl) = v1;
        }
    }
}

// ---------------------------------------------------------------------------
// KD loss partials (2048 deterministic block partials)
// ---------------------------------------------------------------------------
__global__ void __launch_bounds__(256) kd_kernel(const float* __restrict__ s,
                                                 const float* __restrict__ t)
{
    __shared__ float red[256];
    const size_t N4 = (size_t)3 * BB * TT * DD / 4;
    const float4* s4 = (const float4*)s;
    const float4* t4 = (const float4*)t;
    float acc = 0.f;
    for (size_t i = (size_t)blockIdx.x * 256 + threadIdx.x; i < N4; i += 524288) {
        float4 a = __ldg(s4 + i);
        float4 b = __ldg(t4 + i);
        float dx = a.x - b.x, dy = a.y - b.y, dz = a.z - b.z, dw = a.w - b.w;
        acc += dx * dx + dy * dy + dz * dz + dw * dw;
    }
    red[threadIdx.x] = acc;
    __syncthreads();
    for (int o = 128; o; o >>= 1) {
        if (threadIdx.x < o) red[threadIdx.x] += red[threadIdx.x + o];
        __syncthreads();
    }
    if (threadIdx.x == 0) g_kdpart[blockIdx.x] = red[0];
}

// ---------------------------------------------------------------------------
// Persistent BiLSTM recurrence (R13 structure + fused reduce/cell + split barrier).
// 128 blocks = 2 dir x 16 hid-groups(16 hidden) x 4 b-groups(8 batches).
// Per step (4 syncs):
//   stage h into SMEM (coalesced __ldcg, proven R13 path)
//   partials: warp w's 32-wide k-slice, fma2 into part_s (batch stride 80)
//   fused reduce+cell: tid<128 sums 4 gates x 8 slices (conflict-free banks),
//                      activations, publishes h to g_hbuf
//   barrier: red.release arrival EARLY, then overlap g_hs store + gx(s+1)
//            prefetch with other blocks' arrivals, then acquire poll
// ---------------------------------------------------------------------------
__device__ __forceinline__ float sigmoid_f(float x) { return 1.f / (1.f + __expf(-x)); }
__device__ __forceinline__ float tanh_f(float x) {
    x = fminf(15.f, fmaxf(-15.f, x));
    float e = __expf(2.f * x);
    return (e - 1.f) / (e + 1.f);
}

#define PB 80   // part_s batch stride (floats): 64 rows + 16 pad -> bl*80 = 16*bl mod 32

__global__ void __launch_bounds__(256, 1) recur_kernel(
    const float* __restrict__ Whhf, const float* __restrict__ Whhb)
{
    const int tid = threadIdx.x;
    const int w   = tid >> 5;        // 0..7  k-slice (32 k each)
    const int rl  = tid & 31;        // 0..31 local gate-row
    const int blk = blockIdx.x;
    const int dir = blk >> 6;                  // 0..1
    const int hg  = (blk & 63) >> 2;           // 0..15
    const int bg  = blk & 3;                   // 0..3
    const int hidbase = hg * 16;
    const int bbase   = bg * 8;
    const int gidx    = dir * 4 + bg;          // barrier group (16 blocks)

    // local row r in 0..63: gate = r>>4, hid = hidbase + (r&15)
    const int R0 = ((rl >> 4) << 8) + hidbase + (rl & 15);   // global gate row of rl
    // row rl+32 -> R0 + 512

    const float* __restrict__ Whh = dir ? Whhb : Whhf;

    // Load this thread's 2x32 weights into registers (packed f32x2)
    u64 WregA[16], WregB[16];
    {
        const float4* wpA = (const float4*)(Whh + (size_t)R0 * HH + w * 32);
        const float4* wpB = (const float4*)(Whh + (size_t)(R0 + 512) * HH + w * 32);
#pragma unroll
        for (int i = 0; i < 8; i++) {
            float4 va = wpA[i];
            WregA[2 * i]     = pack2(va.x, va.y);
            WregA[2 * i + 1] = pack2(va.z, va.w);
            float4 vb = wpB[i];
            WregB[2 * i]     = pack2(vb.x, vb.y);
            WregB[2 * i + 1] = pack2(vb.z, vb.w);
        }
    }

    __shared__ __align__(16) float h_s[8 * HH];        // 8 KB staged h
    __shared__ float part_s[8 * 8 * PB];               // [w][b][row64 pad PB] 20 KB

    float c_state = 0.f;
    const int bl = tid >> 4;   // cell mapping (tid<128): batch-local 0..7
    const int jj = tid & 15;   //                          hid-local  0..15
    unsigned int* ctr = &g_barg[gidx * 32];

    // gx pointer for this cell thread (advance per step)
    const float* gxbase = g_gx + ((size_t)dir * TT * BB + bbase + bl) * G4 + hidbase + jj;

    // prefetch gx for s = 0
    float gg0 = 0.f, gg1 = 0.f, gg2 = 0.f, gg3 = 0.f;
    if (tid < 128) {
        const int t0 = dir ? (TT - 1) : 0;
        const float* gxp = gxbase + (size_t)t0 * BB * G4;
        gg0 = __ldg(gxp);
        gg1 = __ldg(gxp + 256);
        gg2 = __ldg(gxp + 512);
        gg3 = __ldg(gxp + 768);
    }

    for (int s = 0; s < TT; s++) {
        const int t = dir ? (TT - 1 - s) : s;

        // ---- stage h (8 batches x 256 fp32, L2-coherent) ----
        {
            const float4* src = (const float4*)(g_hbuf +
                ((size_t)((s & 1) * 2 + dir) * BB + bbase) * HH);
            float4* dst4 = (float4*)h_s;
            dst4[tid]       = __ldcg(src + tid);
            dst4[tid + 256] = __ldcg(src + tid + 256);
        }
        __syncthreads();

        // ---- partial dot products over this warp's k-slice ----
#pragma unroll 2
        for (int b = 0; b < 8; b++) {
            const u64* h2 = (const u64*)(h_s + b * HH + w * 32);
            u64 accA = 0ull, accB = 0ull;
#pragma unroll
            for (int i = 0; i < 16; i++) {
                u64 hv = h2[i];
                fma2(accA, WregA[i], hv);
                fma2(accB, WregB[i], hv);
            }
            float2 fa = unpack2(accA);
            float2 fb = unpack2(accB);
            part_s[w * (8 * PB) + b * PB + rl]      = fa.x + fa.y;
            part_s[w * (8 * PB) + b * PB + 32 + rl] = fb.x + fb.y;
        }
        __syncthreads();

        // ---- fused reduce + cell update (tid < 128 owns (bl, jj)) ----
        float h_out = 0.f;
        if (tid < 128) {
            float gi = gg0, gf = gg1, gc = gg2, go = gg3;
#pragma unroll
            for (int q = 0; q < 8; q++) {
                const float* ps = part_s + q * (8 * PB) + bl * PB + jj;
                gi += ps[0];
                gf += ps[16];
                gc += ps[32];
                go += ps[48];
            }
            float si = sigmoid_f(gi);
            float sf = sigmoid_f(gf);
            float so = sigmoid_f(go);
            c_state = sf * c_state + si * tanh_f(gc);
            h_out = so * tanh_f(c_state);
            __stcg(g_hbuf + ((size_t)(((s + 1) & 1) * 2 + dir) * BB + bbase + bl) * HH
                   + hidbase + jj, h_out);
        }
        __syncthreads();

        // ---- barrier arrival (publishes g_hbuf stores via sync + release) ----
        if (tid == 0)
            asm volatile("red.release.gpu.global.add.u32 [%0], %1;" :: "l"(ctr), "r"(1u) : "memory");

        // ---- overlap window: history store + next-step gx prefetch ----
        if (tid < 128) {
            g_hs[(((size_t)dir * BB + bbase + bl) * TT + t) * HH + hidbase + jj] = h_out;
            if (s + 1 < TT) {
                const int t2 = dir ? (TT - 2 - s) : (s + 1);
                const float* gxp = gxbase + (size_t)t2 * BB * G4;
                gg0 = __ldg(gxp);
                gg1 = __ldg(gxp + 256);
                gg2 = __ldg(gxp + 512);
                gg3 = __ldg(gxp + 768);
            }
        }

        // ---- barrier poll ----
        if (tid == 0) {
            unsigned target = 16u * (unsigned)(s + 1);
            unsigned v;
            do {
                asm volatile("ld.acquire.gpu.global.u32 %0, [%1];" : "=r"(v) : "l"(ctr) : "memory");
            } while (v < target);
        }
        __syncthreads();
    }
}

// ---------------------------------------------------------------------------
// Logits: one warp per (b,t) row
// ---------------------------------------------------------------------------
__global__ void __launch_bounds__(256) logits_kernel(
    const float* __restrict__ Wcls, const float* __restrict__ bcls)
{
    __shared__ __align__(16) float Ws[2 * 512];
    const int tid = threadIdx.x;
    for (int i = tid; i < 1024; i += 256) Ws[i] = Wcls[i];
    __syncthreads();

    const int warp = tid >> 5, lane = tid & 31;
    const int row = blockIdx.x * 8 + warp;
    const int b = row / TT, t = row % TT;

    const float4* hf  = (const float4*)(g_hs + ((size_t)b * TT + t) * HH);
    const float4* hb  = (const float4*)(g_hs + (((size_t)BB + b) * TT + t) * HH);
    const float4* W0  = (const float4*)Ws;
    const float4* W1  = (const float4*)(Ws + 512);

    float a0 = 0.f, a1 = 0.f;
#pragma unroll
    for (int q = 0; q < 2; q++) {
        int u = lane + q * 32;
        float4 v  = hf[u];
        float4 w0 = W0[u];
        float4 w1 = W1[u];
        a0 += v.x * w0.x + v.y * w0.y + v.z * w0.z + v.w * w0.w;
        a1 += v.x * w1.x + v.y * w1.y + v.z * w1.z + v.w * w1.w;
    }
#pragma unroll
    for (int q = 0; q < 2; q++) {
        int u = lane + q * 32;
        float4 v  = hb[u];
        float4 w0 = W0[64 + u];
        float4 w1 = W1[64 + u];
        a0 += v.x * w0.x + v.y * w0.y + v.z * w0.z + v.w * w0.w;
        a1 += v.x * w1.x + v.y * w1.y + v.z * w1.z + v.w * w1.w;
    }
#pragma unroll
    for (int o = 16; o; o >>= 1) {
        a0 += __shfl_down_sync(0xffffffffu, a0, o);
        a1 += __shfl_down_sync(0xffffffffu, a1, o);
    }
    if (lane == 0) {
        g_logits[row * 2]     = a0 + bcls[0];
        g_logits[row * 2 + 1] = a1 + bcls[1];
    }
}

// ---------------------------------------------------------------------------
// CRF forward + numerator + final loss
// ---------------------------------------------------------------------------
__device__ __forceinline__ float lse2(float a, float b) {
    float m = fmaxf(a, b);
    return m + log1pf(__expf(-fabsf(a - b)));
}

__global__ void crf_kernel(const float* __restrict__ cst,
                           const float* __restrict__ cen,
                           const float* __restrict__ ctr,
                           const int* __restrict__ labels,
                           const int* __restrict__ mask,
                           float* __restrict__ out)
{
    const int b = threadIdx.x;
    const float tr00 = ctr[0], tr01 = ctr[1], tr10 = ctr[2], tr11 = ctr[3];
    const float* em = g_logits + (size_t)b * TT * 2;
    const int* lab = labels + (size_t)b * TT;
    const int* msk = mask   + (size_t)b * TT;

    float e0 = em[0], e1 = em[1];
    float a0 = cst[0] + e0, a1 = cst[1] + e1;

    int tag_prev = lab[0]; if (tag_prev == -100) tag_prev = 0;
    float num = cst[tag_prev] + (tag_prev ? e1 : e0);
    int cnt = 1;

    for (int t = 1; t < TT; t++) {
        int mraw = msk[t];
        float mt = (mraw != 0) ? 1.f : 0.f;
        float em0 = em[t * 2], em1 = em[t * 2 + 1];
        int tag = lab[t]; if (tag == -100) tag = 0;

        float trs = tag ? (tag_prev ? tr11 : tr01) : (tag_prev ? tr10 : tr00);
        float ems = tag ? em1 : em0;
        num += mt * (trs + ems);
        tag_prev = tag;
        cnt += (mraw != 0);

        float n0 = em0 + lse2(a0 + tr00, a1 + tr10);
        float n1 = em1 + lse2(a0 + tr01, a1 + tr11);
        if (mraw != 0) { a0 = n0; a1 = n1; }
    }
    int lt = lab[cnt - 1]; if (lt == -100) lt = 0;
    num += cen[lt];

    float logZ = lse2(a0 + cen[0], a1 + cen[1]);
    float v = num - logZ;

    float kdp = 0.f;
#pragma unroll
    for (int i = 0; i < 64; i++) kdp += g_kdpart[b * 64 + i];

#pragma unroll
    for (int o = 16; o; o >>= 1) {
        v   += __shfl_down_sync(0xffffffffu, v, o);
        kdp += __shfl_down_sync(0xffffffffu, kdp, o);
    }
    if (b == 0) {
        float span = -v / (float)BB;
        float kd = kdp / ((float)3 * BB * TT * DD);
        out[0] = 0.5f * span + 0.5f * kd;
    }
}

// ---------------------------------------------------------------------------
// Launch
// ---------------------------------------------------------------------------
extern "C" void kernel_launch(void* const* d_in, const int* in_sizes, int n_in,
                              void* d_out, int out_size)
{
    const float* top  = (const float*)d_in[0];
    const float* sfe  = (const float*)d_in[1];
    const float* tfe  = (const float*)d_in[2];
    const float* Wihf = (const float*)d_in[3];
    const float* Whhf = (const float*)d_in[4];
    const float* bihf = (const float*)d_in[5];
    const float* bhhf = (const float*)d_in[6];
    const float* Wihb = (const float*)d_in[7];
    const float* Whhb = (const float*)d_in[8];
    const float* bihb = (const float*)d_in[9];
    const float* bhhb = (const float*)d_in[10];
    const float* Wcls = (const float*)d_in[11];
    const float* bcls = (const float*)d_in[12];
    const float* cst  = (const float*)d_in[13];
    const float* cen  = (const float*)d_in[14];
    const float* ctr  = (const float*)d_in[15];
    const int*   lab  = (const int*)d_in[16];
    const int*   msk  = (const int*)d_in[17];
    float* out = (float*)d_out;

    cudaFuncSetAttribute(gemm_tc_kernel, cudaFuncAttributeMaxDynamicSharedMemorySize, GEMM_SMEM);

    init_kernel<<<32, 256>>>();

    cvt_kernel<<<2048, 256>>>(top, Wihf, Wihb);

    dim3 gg(14336 / 128, G4 / 128, 2);               // 112 x 8 x 2
    gemm_tc_kernel<<<gg, 256, GEMM_SMEM>>>(bihf, bhhf, bihb, bhhb);

    kd_kernel<<<2048, 256>>>(sfe, tfe);

    recur_kernel<<<128, 256>>>(Whhf, Whhb);

    logits_kernel<<<(BB * TT) / 8, 256>>>(Wcls, bcls);

    crf_kernel<<<1, 32>>>(cst, cen, ctr, lab, msk, out);
}

// round 16
// speedup vs baseline: 1.7635x; 1.0795x over previous
#include <cuda_runtime.h>
#include <cuda_bf16.h>
#include <cstdint>

// ---------------------------------------------------------------------------
// Problem constants
// ---------------------------------------------------------------------------
#define BB   32      // batch
#define TT   448     // time
#define DD   768     // input dim
#define HH   256     // hidden
#define G4   1024    // 4*H
#define NTAGS 2

typedef unsigned long long u64;

// ---------------------------------------------------------------------------
// Scratch (device globals; allocation-free)
// ---------------------------------------------------------------------------
__device__ float g_gx[2u * TT * BB * G4];          // [dir][t][b][4H]  117 MB
__device__ float g_hs[2u * BB * TT * HH];          // [dir][b][t][h]   29 MB
__device__ float g_hbuf[2 * 2 * BB * HH];          // [phase][dir][b][h] fp32
__device__ float g_logits[BB * TT * NTAGS];
__device__ float g_kdpart[2048];
__device__ unsigned int g_barg[256];               // 8 group counters, 128B apart
__device__ __nv_bfloat16 g_xb[(size_t)BB * TT * DD];      // bf16 x     22 MB
__device__ __nv_bfloat16 g_wb[(size_t)2 * G4 * DD];       // bf16 W_ih   3 MB

// ---------------------------------------------------------------------------
// f32x2 packed helpers (recurrence path)
// ---------------------------------------------------------------------------
__device__ __forceinline__ u64 pack2(float lo, float hi) {
    u64 r; asm("mov.b64 %0, {%1, %2};" : "=l"(r) : "f"(lo), "f"(hi)); return r;
}
__device__ __forceinline__ float2 unpack2(u64 v) {
    float2 f; asm("mov.b64 {%0, %1}, %2;" : "=f"(f.x), "=f"(f.y) : "l"(v)); return f;
}
__device__ __forceinline__ void fma2(u64 &acc, u64 a, u64 b) {
    asm("fma.rn.f32x2 %0, %1, %2, %3;" : "=l"(acc) : "l"(a), "l"(b), "l"(acc));
}

// ---------------------------------------------------------------------------
// mma.sync / ldmatrix / cp.async helpers (plain sm_80+ PTX, safe on sm_103)
// ---------------------------------------------------------------------------
__device__ __forceinline__ uint32_t smem_u32(const void* p) {
    uint32_t a;
    asm("{ .reg .u64 t; cvta.to.shared.u64 t, %1; cvt.u32.u64 %0, t; }" : "=r"(a) : "l"(p));
    return a;
}
#define CP_ASYNC16(dst, src) \
    asm volatile("cp.async.cg.shared.global [%0], [%1], 16;" :: "r"(dst), "l"(src))
#define CP_COMMIT() asm volatile("cp.async.commit_group;")
#define CP_WAIT(n)  asm volatile("cp.async.wait_group %0;" :: "n"(n))

__device__ __forceinline__ void ldsm_x4(uint32_t &r0, uint32_t &r1, uint32_t &r2, uint32_t &r3,
                                        uint32_t addr) {
    asm volatile("ldmatrix.sync.aligned.m8n8.x4.shared.b16 {%0,%1,%2,%3}, [%4];"
                 : "=r"(r0), "=r"(r1), "=r"(r2), "=r"(r3) : "r"(addr));
}
__device__ __forceinline__ void mma_16816(float* d, const uint32_t* a, uint32_t b0, uint32_t b1) {
    asm volatile("mma.sync.aligned.m16n8k16.row.col.f32.bf16.bf16.f32 "
                 "{%0,%1,%2,%3}, {%4,%5,%6,%7}, {%8,%9}, {%0,%1,%2,%3};"
                 : "+f"(d[0]), "+f"(d[1]), "+f"(d[2]), "+f"(d[3])
                 : "r"(a[0]), "r"(a[1]), "r"(a[2]), "r"(a[3]), "r"(b0), "r"(b1));
}
__device__ __forceinline__ uint32_t sw128(uint32_t off) {
    return off ^ ((off >> 3) & 0x70u);
}

// ---------------------------------------------------------------------------
// cvt + init fused: reset barriers, zero h state, fp32->bf16 of x and W_ih
// ---------------------------------------------------------------------------
#define NX4  ((size_t)BB * TT * DD / 4)     // 2,752,512
#define NW4  ((size_t)G4 * DD / 4)          //   196,608
__global__ void __launch_bounds__(256) cvt_kernel(const float* __restrict__ x,
                                                  const float* __restrict__ Wf,
                                                  const float* __restrict__ Wb)
{
    // fused init (consumers run later in the same stream)
    if (blockIdx.x == 0 && threadIdx.x < 256) g_barg[threadIdx.x] = 0u;
    if (blockIdx.x < 32) {
        uint4* p = (uint4*)g_hbuf;            // 8192 uint4 total
        p[blockIdx.x * 256 + threadIdx.x] = make_uint4(0u, 0u, 0u, 0u);
    }

    const size_t total = NX4 + 2 * NW4;
    const size_t stride = (size_t)gridDim.x * 256;
    for (size_t i = (size_t)blockIdx.x * 256 + threadIdx.x; i < total; i += stride) {
        const float4* src; uint2* dst; size_t j;
        if (i < NX4)            { src = (const float4*)x;  j = i;             dst = (uint2*)g_xb; }
        else if (i < NX4 + NW4) { src = (const float4*)Wf; j = i - NX4;       dst = (uint2*)g_wb; }
        else                    { src = (const float4*)Wb; j = i - NX4 - NW4; dst = (uint2*)g_wb + NW4; }
        float4 v = __ldg(src + j);
        __nv_bfloat162 p0 = __floats2bfloat162_rn(v.x, v.y);
        __nv_bfloat162 p1 = __floats2bfloat162_rn(v.z, v.w);
        dst[j] = make_uint2(*(uint32_t*)&p0, *(uint32_t*)&p1);
    }
}

// ---------------------------------------------------------------------------
// bf16 HMMA input GEMM: gx[dir][t][b][n] = x[b,t,:] . Wih[dir][n,:] + biases
// Block: 128x128 tile, 8 warps (warp tile 32x64), K in 12 chunks of 64,
// cp.async THREE-stage SW128-swizzled SMEM, ldmatrix fragment loads.
// ---------------------------------------------------------------------------
#define SM_BIAS  0           // 128 floats (512 B)
#define SM_A0    1024
#define SM_B0    (SM_A0 + 16384)
#define SM_A1    (SM_B0 + 16384)
#define SM_B1    (SM_A1 + 16384)
#define SM_A2    (SM_B1 + 16384)
#define SM_B2    (SM_A2 + 16384)
#define SM_END   (SM_B2 + 16384)
#define GEMM_SMEM (SM_END + 1024)

__global__ void __launch_bounds__(256) gemm_tc_kernel(
    const float* __restrict__ bihf, const float* __restrict__ bhhf,
    const float* __restrict__ bihb, const float* __restrict__ bhhb)
{
    extern __shared__ char smem_raw[];
    uint32_t raw = smem_u32(smem_raw);
    uint32_t pad = (1024u - (raw & 1023u)) & 1023u;
    uint32_t sb = raw + pad;
    char* sm = smem_raw + pad;

    const int tid  = threadIdx.x;
    const int wid  = tid >> 5, lane = tid & 31;
    const int wm   = wid & 3;          // 0..3 -> m offset wm*32
    const int wn   = wid >> 2;         // 0..1 -> n offset wn*64
    const int dir  = blockIdx.z;
    const int m0   = blockIdx.x * 128;
    const int n0   = blockIdx.y * 128;

    const __nv_bfloat16* __restrict__ Wsrc = g_wb + (size_t)dir * G4 * DD;
    const float* __restrict__ bi = dir ? bihb : bihf;
    const float* __restrict__ bh = dir ? bhhb : bhhf;
    float* bias_s = (float*)(sm + SM_BIAS);

    if (tid < 128) bias_s[tid] = bi[n0 + tid] + bh[n0 + tid];

    const uint32_t Aoff[3] = { SM_A0, SM_A1, SM_A2 };
    const uint32_t Boff[3] = { SM_B0, SM_B1, SM_B2 };

    auto load_chunk = [&](int c) {
        const int buf = c % 3;
        const int kc  = c * 64;
        uint32_t Ab = sb + Aoff[buf];
        uint32_t Bb = sb + Boff[buf];
#pragma unroll
        for (int it = 0; it < 4; it++) {
            int idx = tid + it * 256;          // 0..1023
            int r  = idx >> 3;                 // row 0..127
            int cg = idx & 7;                  // 16B col group
            uint32_t swo = sw128((uint32_t)(r * 128 + cg * 16));
            const char* srcA = (const char*)g_xb + ((size_t)(m0 + r) * DD + kc + cg * 8) * 2;
            const char* srcB = (const char*)Wsrc + ((size_t)(n0 + r) * DD + kc + cg * 8) * 2;
            CP_ASYNC16(Ab + swo, srcA);
            CP_ASYNC16(Bb + swo, srcB);
        }
        CP_COMMIT();
    };

    float acc[2][8][4];
#pragma unroll
    for (int i = 0; i < 2; i++)
#pragma unroll
        for (int j = 0; j < 8; j++)
#pragma unroll
            for (int q = 0; q < 4; q++) acc[i][j][q] = 0.f;

    const int a_row_base = wm * 32 + (lane & 15);
    const int a_cb       = (lane >> 4) * 16;
    const int b_row_base = wn * 64 + (lane & 7) + ((lane >> 4) << 3);
    const int b_cb       = ((lane >> 3) & 1) * 16;

    load_chunk(0);
    load_chunk(1);
    load_chunk(2);

    for (int c = 0; c < 12; c++) {
        if (c < 10)      { CP_WAIT(2); }
        else if (c == 10){ CP_WAIT(1); }
        else             { CP_WAIT(0); }
        __syncthreads();
        const uint32_t Ab = sb + Aoff[c % 3];
        const uint32_t Bb = sb + Boff[c % 3];
#pragma unroll
        for (int ks = 0; ks < 4; ks++) {
            const int kbyte = ks * 32;
            uint32_t a[2][4];
#pragma unroll
            for (int mf = 0; mf < 2; mf++) {
                uint32_t off = (uint32_t)((a_row_base + mf * 16) * 128 + a_cb + kbyte);
                ldsm_x4(a[mf][0], a[mf][1], a[mf][2], a[mf][3], Ab + sw128(off));
            }
#pragma unroll
            for (int nf2 = 0; nf2 < 4; nf2++) {
                uint32_t b0, b1, b2, b3;
                uint32_t off = (uint32_t)((b_row_base + nf2 * 16) * 128 + b_cb + kbyte);
                ldsm_x4(b0, b1, b2, b3, Bb + sw128(off));
#pragma unroll
                for (int mf = 0; mf < 2; mf++) {
                    mma_16816(acc[mf][nf2 * 2 + 0], a[mf], b0, b1);
                    mma_16816(acc[mf][nf2 * 2 + 1], a[mf], b2, b3);
                }
            }
        }
        __syncthreads();
        if (c + 3 < 12) load_chunk(c + 3);
    }

    const int qq = lane & 3;
#pragma unroll
    for (int mf = 0; mf < 2; mf++) {
        const int rloc0 = wm * 32 + mf * 16 + (lane >> 2);
        const int row0  = m0 + rloc0;
        const int row1  = row0 + 8;
        const int b0i = row0 / TT, t0 = row0 % TT;
        const int b1i = row1 / TT, t1 = row1 % TT;
        float* dst0 = g_gx + (((size_t)dir * TT + t0) * BB + b0i) * G4 + n0;
        float* dst1 = g_gx + (((size_t)dir * TT + t1) * BB + b1i) * G4 + n0;
#pragma unroll
        for (int nf = 0; nf < 8; nf++) {
            const int cl = wn * 64 + nf * 8 + 2 * qq;
            float bx = bias_s[cl], by = bias_s[cl + 1];
            float2 v0 = { acc[mf][nf][0] + bx, acc[mf][nf][1] + by };
            float2 v1 = { acc[mf][nf][2] + bx, acc[mf][nf][3] + by };
            *(float2*)(dst0 + cl) = v0;
            *(float2*)(dst1 + cl) = v1;
        }
    }
}

// ---------------------------------------------------------------------------
// KD loss partials (2048 deterministic block partials)
// ---------------------------------------------------------------------------
__global__ void __launch_bounds__(256) kd_kernel(const float* __restrict__ s,
                                                 const float* __restrict__ t)
{
    __shared__ float red[256];
    const size_t N4 = (size_t)3 * BB * TT * DD / 4;
    const float4* s4 = (const float4*)s;
    const float4* t4 = (const float4*)t;
    float acc = 0.f;
    for (size_t i = (size_t)blockIdx.x * 256 + threadIdx.x; i < N4; i += 524288) {
        float4 a = __ldg(s4 + i);
        float4 b = __ldg(t4 + i);
        float dx = a.x - b.x, dy = a.y - b.y, dz = a.z - b.z, dw = a.w - b.w;
        acc += dx * dx + dy * dy + dz * dz + dw * dw;
    }
    red[threadIdx.x] = acc;
    __syncthreads();
    for (int o = 128; o; o >>= 1) {
        if (threadIdx.x < o) red[threadIdx.x] += red[threadIdx.x + o];
        __syncthreads();
    }
    if (threadIdx.x == 0) g_kdpart[blockIdx.x] = red[0];
}

// ---------------------------------------------------------------------------
// Persistent BiLSTM recurrence (R13 structure + shuffle-fused cell).
// 128 blocks = 2 dir x 16 hid-groups(16 hidden) x 4 b-groups(8 batches).
// Thread (w = k-slice / batch, rl) owns gate rows rl and rl+32 of 64.
// Lane pair (rl, rl+16) of warp w holds all 4 gates of cell (b=w, j=rl&15):
//   rl<16:  rows  = gate i (R0) and gate g (R0+512)
//   rl>=16: rows  = gate f and gate o
// One shfl_xor(16) replaces the gate_s SMEM round-trip + one sync.
// Barrier: per-(dir,bg) 16-block counter, red.release + acquire poll (proven).
// ---------------------------------------------------------------------------
__device__ __forceinline__ float sigmoid_f(float x) { return 1.f / (1.f + __expf(-x)); }
__device__ __forceinline__ float tanh_f(float x) {
    x = fminf(15.f, fmaxf(-15.f, x));
    float e = __expf(2.f * x);
    return (e - 1.f) / (e + 1.f);
}

__global__ void __launch_bounds__(256, 1) recur_kernel(
    const float* __restrict__ Whhf, const float* __restrict__ Whhb)
{
    const int tid = threadIdx.x;
    const int w   = tid >> 5;        // 0..7  k-slice (32 k each) / batch idx
    const int rl  = tid & 31;        // 0..31 local gate-row
    const int blk = blockIdx.x;
    const int dir = blk >> 6;                  // 0..1
    const int hg  = (blk & 63) >> 2;           // 0..15
    const int bg  = blk & 3;                   // 0..3
    const int hidbase = hg * 16;
    const int bbase   = bg * 8;
    const int gidx    = dir * 4 + bg;          // barrier group (16 blocks)

    // local row r in 0..63: gate = r>>4, hid = hidbase + (r&15)
    const int R0 = ((rl >> 4) << 8) + hidbase + (rl & 15);   // global gate row of rl
    // row rl+32 -> R0 + 512

    const float* __restrict__ Whh = dir ? Whhb : Whhf;

    // Load this thread's 2x32 weights into registers (packed f32x2)
    u64 WregA[16], WregB[16];
    {
        const float4* wpA = (const float4*)(Whh + (size_t)R0 * HH + w * 32);
        const float4* wpB = (const float4*)(Whh + (size_t)(R0 + 512) * HH + w * 32);
#pragma unroll
        for (int i = 0; i < 8; i++) {
            float4 va = wpA[i];
            WregA[2 * i]     = pack2(va.x, va.y);
            WregA[2 * i + 1] = pack2(va.z, va.w);
            float4 vb = wpB[i];
            WregB[2 * i]     = pack2(vb.x, vb.y);
            WregB[2 * i + 1] = pack2(vb.z, vb.w);
        }
    }

    __shared__ __align__(16) float h_s[8 * HH];        // 8 KB staged h
    __shared__ float part_s[8 * 8 * 64];               // [w][b][row] 16 KB

    float c_state = 0.f;                               // live in lanes rl<16
    unsigned int* ctr = &g_barg[gidx * 32];

    for (int s = 0; s < TT; s++) {
        const int t = dir ? (TT - 1 - s) : s;

        // ---- stage h (8 batches x 256 fp32, L2-coherent) ----
        {
            const float4* src = (const float4*)(g_hbuf +
                ((size_t)((s & 1) * 2 + dir) * BB + bbase) * HH);
            float4* dst4 = (float4*)h_s;
            dst4[tid]       = __ldcg(src + tid);
            dst4[tid + 256] = __ldcg(src + tid + 256);
        }
        __syncthreads();

        // ---- prefetch gx for the two rows this thread reduces (b=w) ----
        float gx0, gx1;
        {
            const float* gxp = g_gx + (((size_t)dir * TT + t) * BB + bbase + w) * G4 + R0;
            gx0 = __ldg(gxp);
            gx1 = __ldg(gxp + 512);
        }

        // ---- partial dot products over this warp's k-slice ----
#pragma unroll 2
        for (int b = 0; b < 8; b++) {
            const u64* h2 = (const u64*)(h_s + b * HH + w * 32);
            u64 accA = 0ull, accB = 0ull;
#pragma unroll
            for (int i = 0; i < 16; i++) {
                u64 hv = h2[i];
                fma2(accA, WregA[i], hv);
                fma2(accB, WregB[i], hv);
            }
            float2 fa = unpack2(accA);
            float2 fb = unpack2(accB);
            part_s[w * 512 + b * 64 + rl]      = fa.x + fa.y;
            part_s[w * 512 + b * 64 + 32 + rl] = fb.x + fb.y;
        }
        __syncthreads();

        // ---- cross-slice reduction (conflict-free) + shuffle-fused cell ----
        {
            float s0 = gx0, s1 = gx1;
#pragma unroll
            for (int q = 0; q < 8; q++) {
                s0 += part_s[q * 512 + w * 64 + rl];
                s1 += part_s[q * 512 + w * 64 + 32 + rl];
            }
            // lane pair exchange: lanes <16 receive (gf, go) from lanes +16
            float o0 = __shfl_xor_sync(0xffffffffu, s0, 16);
            float o1 = __shfl_xor_sync(0xffffffffu, s1, 16);
            if (rl < 16) {
                // s0 = gate i, s1 = gate g, o0 = gate f, o1 = gate o
                float si = sigmoid_f(s0);
                float sf = sigmoid_f(o0);
                float so = sigmoid_f(o1);
                c_state = sf * c_state + si * tanh_f(s1);
                float h = so * tanh_f(c_state);
                int bglob = bbase + w;
                int hglob = hidbase + rl;
                __stcg(g_hbuf + ((size_t)(((s + 1) & 1) * 2 + dir) * BB + bglob) * HH + hglob, h);
                g_hs[(((size_t)dir * BB + bglob) * TT + t) * HH + hglob] = h;
            }
        }
        __syncthreads();

        // ---- group barrier: release arrival + acquire poll (16 blocks) ----
        if (tid == 0) {
            asm volatile("red.release.gpu.global.add.u32 [%0], %1;" :: "l"(ctr), "r"(1u) : "memory");
            unsigned target = 16u * (unsigned)(s + 1);
            unsigned v;
            do {
                asm volatile("ld.acquire.gpu.global.u32 %0, [%1];" : "=r"(v) : "l"(ctr) : "memory");
            } while (v < target);
        }
        __syncthreads();
    }
}

// ---------------------------------------------------------------------------
// Logits: one warp per (b,t) row
// ---------------------------------------------------------------------------
__global__ void __launch_bounds__(256) logits_kernel(
    const float* __restrict__ Wcls, const float* __restrict__ bcls)
{
    __shared__ __align__(16) float Ws[2 * 512];
    const int tid = threadIdx.x;
    for (int i = tid; i < 1024; i += 256) Ws[i] = Wcls[i];
    __syncthreads();

    const int warp = tid >> 5, lane = tid & 31;
    const int row = blockIdx.x * 8 + warp;
    const int b = row / TT, t = row % TT;

    const float4* hf  = (const float4*)(g_hs + ((size_t)b * TT + t) * HH);
    const float4* hb  = (const float4*)(g_hs + (((size_t)BB + b) * TT + t) * HH);
    const float4* W0  = (const float4*)Ws;
    const float4* W1  = (const float4*)(Ws + 512);

    float a0 = 0.f, a1 = 0.f;
#pragma unroll
    for (int q = 0; q < 2; q++) {
        int u = lane + q * 32;
        float4 v  = hf[u];
        float4 w0 = W0[u];
        float4 w1 = W1[u];
        a0 += v.x * w0.x + v.y * w0.y + v.z * w0.z + v.w * w0.w;
        a1 += v.x * w1.x + v.y * w1.y + v.z * w1.z + v.w * w1.w;
    }
#pragma unroll
    for (int q = 0; q < 2; q++) {
        int u = lane + q * 32;
        float4 v  = hb[u];
        float4 w0 = W0[64 + u];
        float4 w1 = W1[64 + u];
        a0 += v.x * w0.x + v.y * w0.y + v.z * w0.z + v.w * w0.w;
        a1 += v.x * w1.x + v.y * w1.y + v.z * w1.z + v.w * w1.w;
    }
#pragma unroll
    for (int o = 16; o; o >>= 1) {
        a0 += __shfl_down_sync(0xffffffffu, a0, o);
        a1 += __shfl_down_sync(0xffffffffu, a1, o);
    }
    if (lane == 0) {
        g_logits[row * 2]     = a0 + bcls[0];
        g_logits[row * 2 + 1] = a1 + bcls[1];
    }
}

// ---------------------------------------------------------------------------
// CRF forward + numerator + final loss
// ---------------------------------------------------------------------------
__device__ __forceinline__ float lse2(float a, float b) {
    float m = fmaxf(a, b);
    return m + log1pf(__expf(-fabsf(a - b)));
}

__global__ void crf_kernel(const float* __restrict__ cst,
                           const float* __restrict__ cen,
                           const float* __restrict__ ctr,
                           const int* __restrict__ labels,
                           const int* __restrict__ mask,
                           float* __restrict__ out)
{
    const int b = threadIdx.x;
    const float tr00 = ctr[0], tr01 = ctr[1], tr10 = ctr[2], tr11 = ctr[3];
    const float* em = g_logits + (size_t)b * TT * 2;
    const int* lab = labels + (size_t)b * TT;
    const int* msk = mask   + (size_t)b * TT;

    float e0 = em[0], e1 = em[1];
    float a0 = cst[0] + e0, a1 = cst[1] + e1;

    int tag_prev = lab[0]; if (tag_prev == -100) tag_prev = 0;
    float num = cst[tag_prev] + (tag_prev ? e1 : e0);
    int cnt = 1;

    for (int t = 1; t < TT; t++) {
        int mraw = msk[t];
        float mt = (mraw != 0) ? 1.f : 0.f;
        float em0 = em[t * 2], em1 = em[t * 2 + 1];
        int tag = lab[t]; if (tag == -100) tag = 0;

        float trs = tag ? (tag_prev ? tr11 : tr01) : (tag_prev ? tr10 : tr00);
        float ems = tag ? em1 : em0;
        num += mt * (trs + ems);
        tag_prev = tag;
        cnt += (mraw != 0);

        float n0 = em0 + lse2(a0 + tr00, a1 + tr10);
        float n1 = em1 + lse2(a0 + tr01, a1 + tr11);
        if (mraw != 0) { a0 = n0; a1 = n1; }
    }
    int lt = lab[cnt - 1]; if (lt == -100) lt = 0;
    num += cen[lt];

    float logZ = lse2(a0 + cen[0], a1 + cen[1]);
    float v = num - logZ;

    float kdp = 0.f;
#pragma unroll
    for (int i = 0; i < 64; i++) kdp += g_kdpart[b * 64 + i];

#pragma unroll
    for (int o = 16; o; o >>= 1) {
        v   += __shfl_down_sync(0xffffffffu, v, o);
        kdp += __shfl_down_sync(0xffffffffu, kdp, o);
    }
    if (b == 0) {
        float span = -v / (float)BB;
        float kd = kdp / ((float)3 * BB * TT * DD);
        out[0] = 0.5f * span + 0.5f * kd;
    }
}

// ---------------------------------------------------------------------------
// Launch
// ---------------------------------------------------------------------------
extern "C" void kernel_launch(void* const* d_in, const int* in_sizes, int n_in,
                              void* d_out, int out_size)
{
    const float* top  = (const float*)d_in[0];
    const float* sfe  = (const float*)d_in[1];
    const float* tfe  = (const float*)d_in[2];
    const float* Wihf = (const float*)d_in[3];
    const float* Whhf = (const float*)d_in[4];
    const float* bihf = (const float*)d_in[5];
    const float* bhhf = (const float*)d_in[6];
    const float* Wihb = (const float*)d_in[7];
    const float* Whhb = (const float*)d_in[8];
    const float* bihb = (const float*)d_in[9];
    const float* bhhb = (const float*)d_in[10];
    const float* Wcls = (const float*)d_in[11];
    const float* bcls = (const float*)d_in[12];
    const float* cst  = (const float*)d_in[13];
    const float* cen  = (const float*)d_in[14];
    const float* ctr  = (const float*)d_in[15];
    const int*   lab  = (const int*)d_in[16];
    const int*   msk  = (const int*)d_in[17];
    float* out = (float*)d_out;

    cudaFuncSetAttribute(gemm_tc_kernel, cudaFuncAttributeMaxDynamicSharedMemorySize, GEMM_SMEM);

    cvt_kernel<<<2048, 256>>>(top, Wihf, Wihb);     // init fused in

    dim3 gg(14336 / 128, G4 / 128, 2);               // 112 x 8 x 2
    gemm_tc_kernel<<<gg, 256, GEMM_SMEM>>>(bihf, bhhf, bihb, bhhb);

    kd_kernel<<<2048, 256>>>(sfe, tfe);

    recur_kernel<<<128, 256>>>(Whhf, Whhb);

    logits_kernel<<<(BB * TT) / 8, 256>>>(Wcls, bcls);

    crf_kernel<<<1, 32>>>(cst, cen, ctr, lab, msk, out);
}